// round 9
// baseline (speedup 1.0000x reference)
#include <cuda_runtime.h>

// LegoConv2d GB300 — R8: persistent half-slab units to kill wave quantization.
// Unit u = (b, h, half): feat[64 x 112] = lego[64 x 192] @ X[192 x 112],
// splits i in {2*half, 2*half+1}. Epilogue: one-hot gather, fp32 atomicAdd
// into pre-zeroed out (2 partials per element -> bitwise deterministic).
//
// 128-thr CTAs, warp = 2 rowgroups x 16 lanes x 7 cols (tile 8x7, NO padding,
// all 32 lanes active). smem 70.7KB -> 3 CTAs/SM, 444 workers, 1216 units
// -> 3 units max/worker vs 2.74 ideal (quantization 1.095, was 1.46).

#define BATCH   32
#define IN_C    256
#define OUT_C   256
#define NLEGO   64
#define HIN     56
#define WIN     56
#define HOUT    19
#define WOUT    58
#define KTOT    192
#define KC      48            // 16 channels * 3 taps per chunk
#define NCHUNK  4
#define NCOL    112           // 2 splits * 56 cols per unit
#define NUNITS  (BATCH*HOUT*2)   // 1216
#define NWORK   444              // 3 CTAs/SM * 148

#define LEGO_FL (KTOT*NLEGO)     // 12288 floats (48KB)
#define X_FL    (KC*NCOL)        // 5376 floats (21KB)
#define SMEM_FL (LEGO_FL + X_FL) // 17664 floats = 70656 B

__device__ int   g_idx[4 * OUT_C];
__device__ float g_coef[4 * OUT_C];

// -------- prep: first-max argmax (matches jnp.argmax) + coefficient pick
__global__ void prep_kernel(const float* __restrict__ coefs,
                            const float* __restrict__ comb) {
    int t = blockIdx.x * blockDim.x + threadIdx.x;   // t = i*256 + o
    if (t >= 4 * OUT_C) return;
    const float* c = comb + (size_t)t * NLEGO;
    float bv = c[0];
    int bi = 0;
    #pragma unroll
    for (int n = 1; n < NLEGO; n++) {
        float v = c[n];
        if (v > bv) { bv = v; bi = n; }
    }
    g_idx[t]  = bi;
    g_coef[t] = coefs[(size_t)t * NLEGO + bi];
}

// -------- zero whole output (also provides the exact-zero w=0 / w=57 borders)
#define OUT_F4 ((BATCH*OUT_C*HOUT*WOUT)/4)   // 2,256,896
__global__ void zero_kernel(float4* __restrict__ out) {
    int i = blockIdx.x * 256 + threadIdx.x;
    if (i < OUT_F4) out[i] = make_float4(0.f, 0.f, 0.f, 0.f);
}

extern __shared__ float smem[];

__global__ __launch_bounds__(128, 3)
void main_kernel(const float* __restrict__ x,
                 const float* __restrict__ lego,
                 float* __restrict__ out) {
    const int t    = threadIdx.x;
    const int lane = t & 31;
    const int wid  = t >> 5;

    // warp tiling: rows 8*rg..8*rg+8, cols 7*cg..7*cg+7
    const int rg = 2 * wid + (lane >> 4);   // 0..7
    const int cg = lane & 15;               // 0..15

    float* lego_s = smem;                   // [192][64]  lego_s[k*64+n]
    float* X_s    = smem + LEGO_FL;         // [48][112]  X_s[kk*112 + (i2*56+w)]
    float* feat_s = smem;                   // overlays lego after GEMM (7168 fl)
    int*   idx_s  = (int*)(smem + LEGO_FL);          // 512 ints   (reuses X_s)
    float* coef_s = smem + LEGO_FL + 512;            // 512 floats

    // staging column for X: threads t<112 own col t
    const int sc = (t < NCOL) ? t : 0;
    const int si = sc / 56;                 // local split 0/1
    const int sw = sc - si * 56;

    for (int u = blockIdx.x; u < NUNITS; u += NWORK) {
        const int half = u & 1;
        const int slab = u >> 1;
        const int h = slab % HOUT;
        const int b = slab / HOUT;

        // ---- (re)stage lego: lego_s[k*64+n] = lego[n*192+k]  (L2-resident)
        for (int s = t; s < LEGO_FL; s += 128) {
            int n = s / KTOT;
            int k = s - n * KTOT;
            lego_s[k * NLEGO + n] = lego[s];
        }
        // barrier folded into first chunk's post-staging barrier below

        float acc[8][7];
        #pragma unroll
        for (int r = 0; r < 8; r++)
            #pragma unroll
            for (int j = 0; j < 7; j++) acc[r][j] = 0.f;

        const float* xp = X_s + 7 * cg;

        for (int chunk = 0; chunk < NCHUNK; chunk++) {
            const int c0 = 16 * chunk;      // channel base of this chunk

            // ---- stage X chunk: rows k = (c0+c16)*3 + kh, kk = c16*3+kh
            if (t < NCOL) {
                const float* xb = x +
                    ((size_t)(b * IN_C + (2 * half + si) * 64 + c0) * HIN) * WIN + sw;
                const int y1 = 3 * h * WIN;          // byte-free float offsets
                #pragma unroll 4
                for (int c16 = 0; c16 < 16; c16++) {
                    const float* xr = xb + c16 * (HIN * WIN);
                    float v0 = (h > 0) ? xr[y1 - WIN] : 0.f;
                    float v1 = xr[y1];
                    float v2 = xr[y1 + WIN];
                    float* xs = X_s + (c16 * 3) * NCOL + sc;
                    xs[0]        = v0;
                    xs[NCOL]     = v1;
                    xs[2 * NCOL] = v2;
                }
            }
            __syncthreads();

            // ---- GEMM over chunk: 56 FFMA + 2 LDS.128 + 7 LDS.32 per k-step
            const float* lp = lego_s + (chunk * KC) * NLEGO + 8 * rg;
            #pragma unroll 4
            for (int kk = 0; kk < KC; kk++) {
                float a[8], bb[7];
                *(float4*)&a[0] = *(const float4*)(lp + kk * NLEGO);
                *(float4*)&a[4] = *(const float4*)(lp + kk * NLEGO + 4);
                #pragma unroll
                for (int j = 0; j < 7; j++) bb[j] = xp[kk * NCOL + j];
                #pragma unroll
                for (int r = 0; r < 8; r++)
                    #pragma unroll
                    for (int j = 0; j < 7; j++)
                        acc[r][j] = fmaf(a[r], bb[j], acc[r][j]);
            }
            __syncthreads();
        }

        // ---- dump feat (overlays lego) + stage gather tables (overlay X_s)
        #pragma unroll
        for (int r = 0; r < 8; r++)
            #pragma unroll
            for (int j = 0; j < 7; j++)
                feat_s[(8 * rg + r) * NCOL + 7 * cg + j] = acc[r][j];
        for (int s = t; s < 2 * OUT_C; s += 128) {      // i2 in {0,1}
            int gi = (2 * half + (s >> 8)) * OUT_C + (s & 255);
            idx_s[s]  = g_idx[gi];
            coef_s[s] = g_coef[gi];
        }
        __syncthreads();

        // ---- epilogue: partial over this unit's 2 splits, atomicAdd to out
        for (int s = t; s < OUT_C * 56; s += 128) {
            int o = s / 56;
            int w = s - o * 56;
            int   i0 = idx_s[o],          i1 = idx_s[OUT_C + o];
            float c0f = coef_s[o],        c1f = coef_s[OUT_C + o];
            float v = c0f * feat_s[i0 * NCOL + w]
                    + c1f * feat_s[i1 * NCOL + 56 + w];
            atomicAdd(&out[((size_t)(b * OUT_C + o) * HOUT + h) * WOUT + (w + 1)], v);
        }
        __syncthreads();   // feat/tables must be fully read before next unit restages
    }
}

extern "C" void kernel_launch(void* const* d_in, const int* in_sizes, int n_in,
                              void* d_out, int out_size) {
    const float* x     = (const float*)d_in[0];   // 32*256*56*56
    const float* lego  = (const float*)d_in[1];   // 64*64*3*1
    const float* coefs = (const float*)d_in[2];   // 4*256*64
    const float* comb  = (const float*)d_in[3];   // 4*256*64
    float* out = (float*)d_out;                   // 32*256*19*58

    (void)in_sizes; (void)n_in; (void)out_size;

    cudaFuncSetAttribute(main_kernel,
                         cudaFuncAttributeMaxDynamicSharedMemorySize,
                         SMEM_FL * (int)sizeof(float));

    prep_kernel<<<4, 256>>>(coefs, comb);
    zero_kernel<<<(OUT_F4 + 255) / 256, 256>>>((float4*)out);
    main_kernel<<<NWORK, 128, SMEM_FL * (int)sizeof(float)>>>(x, lego, out);
}